// round 13
// baseline (speedup 1.0000x reference)
#include <cuda_runtime.h>
#include <cstdint>

#define NN 1024
#define HH 512
#define TI 32            // output rows per CTA
#define NWARPS 8
#define NTHREADS (NWARPS*32)
#define RS 16            // ring slots (raw rows); 16*4KB = 64KB dynamic smem
#define ROWB (NN*4)      // bytes per raw row

__device__ __forceinline__ int reflC(int c) {
    if (c < 0) c = -c;
    if (c > HH - 1) c = 2 * (HH - 1) - c;
    return c;
}

// ---- TMA 1D bulk row copy: one instruction stages a whole 4KB row ----
__device__ __forceinline__ void tma_row(uint32_t dst, const float* src, uint32_t mbar) {
    asm volatile(
        "cp.async.bulk.shared::cta.global.mbarrier::complete_tx::bytes [%0], [%1], %2, [%3];"
        :: "r"(dst), "l"(src), "r"((uint32_t)ROWB), "r"(mbar) : "memory");
}
__device__ __forceinline__ void mbar_init(uint32_t mbar, uint32_t cnt) {
    asm volatile("mbarrier.init.shared.b64 [%0], %1;" :: "r"(mbar), "r"(cnt) : "memory");
}
__device__ __forceinline__ void mbar_expect(uint32_t mbar, uint32_t bytes) {
    asm volatile("mbarrier.arrive.expect_tx.shared.b64 _, [%0], %1;"
                 :: "r"(mbar), "r"(bytes) : "memory");
}
__device__ __forceinline__ void mbar_arrive(uint32_t mbar) {
    asm volatile("mbarrier.arrive.shared.b64 _, [%0];" :: "r"(mbar) : "memory");
}
__device__ __forceinline__ void mbar_wait(uint32_t mbar, uint32_t parity) {
    asm volatile(
        "{\n\t.reg .pred P;\n\t"
        "W_%=:\n\t"
        "mbarrier.try_wait.parity.acquire.cta.shared::cta.b64 P, [%0], %1, 0x989680;\n\t"
        "@!P bra W_%=;\n\t"
        "}" :: "r"(mbar), "r"(parity) : "memory");
}

__device__ __forceinline__ void stcs2(float* p, float a, float b) {
    asm volatile("st.global.cs.v2.f32 [%0], {%1,%2};" :: "l"(p), "f"(a), "f"(b) : "memory");
}

struct V4 { float s0, s1, d0, d1; };

// Shuffle-free row lift reading from an smem row (1024 contiguous floats).
__device__ __forceinline__ V4 rowlift(const float* rp,
                                      int loff, int offA, int offC,
                                      bool lEdge, bool rEdge) {
    const float4 B = *reinterpret_cast<const float4*>(rp + loff);   // raw[4j..4j+3]
    const float4 A = *reinterpret_cast<const float4*>(rp + offA);   // raw[4j-4..4j-1]
    const float4 C = *reinterpret_cast<const float4*>(rp + offC);   // raw[4j+4..4j+7]
    float dm1 = A.w - 0.5f * (A.x + B.x);   // d[2j-1]
    float d0  = B.y - 0.5f * (A.z + B.z);   // d[2j]
    float d1  = B.w - 0.5f * (B.x + C.x);   // d[2j+1]
    float d2  = C.y - 0.5f * (B.z + C.z);   // d[2j+2]
    if (lEdge) { dm1 = d1; d0 = B.y - B.z; }   // d[-1]=d[1]; even[-1]=even[1]
    if (rEdge) { d1 = B.w - B.x; d2 = d0; }    // even[512]=even[510]; d[512]=d[510]
    V4 r;
    r.s0 = B.x + 0.25f * (dm1 + d1);
    r.s1 = B.z + 0.25f * (d0 + d2);
    r.d0 = d0; r.d1 = d1;
    return r;
}

__global__ __launch_bounds__(NTHREADS, 3)
void ilwt2d_ws_kernel(const float* __restrict__ x, float* __restrict__ out) {
    extern __shared__ __align__(16) float ring[];   // RS * NN floats
    __shared__ __align__(8) uint64_t mbars[17];     // [0..7] full, [8] prologue, [9..16] empty

    const int tid  = threadIdx.x;
    const int lane = tid & 31;
    const int w    = tid >> 5;
    const int C0   = w * 64;
    const int i0   = blockIdx.x * TI;
    const int img  = blockIdx.y;
    const float* __restrict__ xp = x + (size_t)img * NN * NN;
    const int rbase = 2 * i0 - 4;

    const uint32_t sring = (uint32_t)__cvta_generic_to_shared(ring);
    const uint32_t mb0   = (uint32_t)__cvta_generic_to_shared(&mbars[0]);
    #define FULL(g)  (mb0 + (uint32_t)((g) * 8))
    #define PRO()    (mb0 + 64u)
    #define EMPTY(g) (mb0 + 72u + (uint32_t)((g) * 8))

    if (tid == 0) {
        #pragma unroll
        for (int j = 0; j < 8; ++j) mbar_init(FULL(j), 1);
        mbar_init(PRO(), 1);
        #pragma unroll
        for (int j = 0; j < 8; ++j) mbar_init(EMPTY(j), NWARPS);
    }
    __syncthreads();

    // ---- prologue staging: offsets 0..14 (15 rows) on the prologue barrier ----
    if (tid == 0) {
        mbar_expect(PRO(), 15u * ROWB);
        #pragma unroll
        for (int k = 0; k < 15; ++k) {
            int row = rbase + k;
            row = max(0, min(NN - 1, row));
            tma_row(sring + (uint32_t)((k & (RS-1)) * ROWB), xp + (size_t)row * NN, PRO());
        }
    }

    // consumer column setup
    const int loff = 2 * C0 + 4 * lane;
    const bool lEdge = (loff == 0);
    const bool rEdge = (loff == NN - 4);
    const int offA = lEdge ? loff : loff - 4;
    const int offC = rEdge ? loff : loff + 4;

    #define LIFTS(R) rowlift(ring + (((R) - rbase) & (RS-1)) * NN, \
                             loff, offA, offC, lEdge, rEdge)

    mbar_wait(PRO(), 0);            // prologue rows 0..14 visible

    // ---- prologue: build column-lift pipeline state (reads offsets 0..8) ----
    V4 Ecur  = LIFTS(2 * i0);
    V4 Em    = LIFTS(2 * reflC(i0 - 1));
    V4 Em2   = LIFTS(2 * reflC(i0 - 2));
    V4 Om1   = LIFTS(2 * reflC(i0 - 1) + 1);
    V4 Dprev;
    Dprev.s0 = Om1.s0 - 0.5f * (Em2.s0 + Ecur.s0);
    Dprev.s1 = Om1.s1 - 0.5f * (Em2.s1 + Ecur.s1);
    Dprev.d0 = Om1.d0 - 0.5f * (Em2.d0 + Ecur.d0);
    Dprev.d1 = Om1.d1 - 0.5f * (Em2.d1 + Ecur.d1);
    V4 Enext = LIFTS(2 * reflC(i0 + 1));
    V4 O0    = LIFTS(2 * i0 + 1);
    V4 Dcur;
    Dcur.s0 = O0.s0 - 0.5f * (Em.s0 + Enext.s0);
    Dcur.s1 = O0.s1 - 0.5f * (Em.s1 + Enext.s1);
    Dcur.d0 = O0.d0 - 0.5f * (Em.d0 + Enext.d0);
    Dcur.d1 = O0.d1 - 0.5f * (Em.d1 + Enext.d1);
    __syncthreads();   // all prologue reads done before t=0..3 staging overwrites offsets 0..6

    const int b = img / 3, ch = img - 3 * b;
    const size_t plane = (size_t)HH * HH;
    float* __restrict__ outb = out + (size_t)b * 12 * plane + (size_t)ch * plane;
    const int ocol = C0 + 2 * lane;

    // stage pair (2t+15, 2t+16) into full[t&7]; rows >= 11 here, only bottom clamp needed
    #define STAGEPAIR(t) do {                                                   \
        if (tid == 0) {                                                         \
            mbar_expect(FULL((t) & 7), 2u * ROWB);                              \
            int k1 = 15 + 2*(t), k2 = 16 + 2*(t);                               \
            int r1 = min(NN - 1, rbase + k1);                                   \
            int r2 = min(NN - 1, rbase + k2);                                   \
            tma_row(sring + (uint32_t)((k1 & (RS-1)) * ROWB), xp + (size_t)r1 * NN, FULL((t) & 7)); \
            tma_row(sring + (uint32_t)((k2 & (RS-1)) * ROWB), xp + (size_t)r2 * NN, FULL((t) & 7)); \
        }                                                                       \
    } while (0)

    #define BODY(t)                                                             \
        const int i = i0 + (t);                                                 \
        V4 En2 = LIFTS(2 * reflC(i + 2));                                       \
        V4 Oi1 = LIFTS(2 * reflC(i + 1) + 1);                                   \
        V4 Dnext;                                                               \
        Dnext.s0 = Oi1.s0 - 0.5f * (Ecur.s0 + En2.s0);                          \
        Dnext.s1 = Oi1.s1 - 0.5f * (Ecur.s1 + En2.s1);                          \
        Dnext.d0 = Oi1.d0 - 0.5f * (Ecur.d0 + En2.d0);                          \
        Dnext.d1 = Oi1.d1 - 0.5f * (Ecur.d1 + En2.d1);                          \
        float2 ll = { Ecur.s0 + 0.25f * (Dprev.s0 + Dnext.s0),                  \
                      Ecur.s1 + 0.25f * (Dprev.s1 + Dnext.s1) };                \
        float2 hl = { Ecur.d0 + 0.25f * (Dprev.d0 + Dnext.d0),                  \
                      Ecur.d1 + 0.25f * (Dprev.d1 + Dnext.d1) };                \
        float* op = outb + (size_t)i * HH + ocol;                               \
        stcs2(op,             ll.x, ll.y);                                      \
        stcs2(op + 3 * plane, Dcur.s0, Dcur.s1);                                \
        stcs2(op + 6 * plane, hl.x, hl.y);                                      \
        stcs2(op + 9 * plane, Dcur.d0, Dcur.d1);                                \
        Ecur = Enext; Enext = En2;                                              \
        Dprev = Dcur; Dcur = Dnext;

    // ---- phase 1: t in [0,4) — stage (slots freed by the syncthreads above),
    //      consume prologue-resident data (no full wait), signal empty ----
    #pragma unroll
    for (int t = 0; t < 4; ++t) {
        STAGEPAIR(t);
        BODY(t);
        if (lane == 0) mbar_arrive(EMPTY((t + 4) & 7));   // group consumed by BODY(t)
    }
    // ---- phase 2: t in [4, TI-4) — producer gated by empty ring; consumers by full ----
    for (int t = 4; t < TI - 4; ++t) {
        if (tid == 0) mbar_wait(EMPTY(t & 7), (uint32_t)(((t - 4) >> 3) & 1));
        STAGEPAIR(t);
        mbar_wait(FULL((t - 4) & 7), (uint32_t)(((t - 4) >> 3) & 1));
        BODY(t);
        if (lane == 0) mbar_arrive(EMPTY((t + 4) & 7));
    }
    // ---- phase 3: t in [TI-4, TI) — wait-only tail (no restaging of these groups) ----
    #pragma unroll
    for (int t = TI - 4; t < TI; ++t) {
        mbar_wait(FULL((t - 4) & 7), (uint32_t)(((t - 4) >> 3) & 1));
        BODY(t);
    }
    #undef BODY
    #undef STAGEPAIR
    #undef LIFTS
    #undef FULL
    #undef PRO
    #undef EMPTY
}

extern "C" void kernel_launch(void* const* d_in, const int* in_sizes, int n_in,
                              void* d_out, int out_size) {
    const float* x = (const float*)d_in[0];
    float* out = (float*)d_out;
    const int smem = RS * NN * sizeof(float);   // 65536
    cudaFuncSetAttribute(ilwt2d_ws_kernel,
                         cudaFuncAttributeMaxDynamicSharedMemorySize, smem);
    dim3 grid(HH / TI, 24);   // 16 x 24 = 384 CTAs
    ilwt2d_ws_kernel<<<grid, NTHREADS, smem>>>(x, out);
}